// round 3
// baseline (speedup 1.0000x reference)
#include <cuda_runtime.h>
#include <math_constants.h>

// SoftMinLayer: W = 79998 windows (len 500, step 250); 5 segments of 100;
// banded DTW (|i-j|<=1) over squared-L2 costs C(i,j) = xx_i + yy_j - 2*xy_ij;
// out = mean(exp(-0.01*sqrt(dtw))).
//
// Block = 128 threads = 64 windows (2 threads per window; thread h owns
// element-half h of every segment). x staged to smem coalesced; scalar LDS
// reads are bank-conflict-free (odd rotation trick for h=1). 18 FMA
// accumulators per thread; one shfl.xor(1) per accumulator to combine the
// pair; DTW fully in registers per thread.

#define SEGC   5
#define WPB    64
#define TPB    128
#define TILE_F (WPB * 250 + 250)   // 16250 floats

__device__ float g_yy[SEGC];

__global__ void init_kernel(const float* __restrict__ S, float* __restrict__ out) {
    const int warp = threadIdx.x >> 5, lane = threadIdx.x & 31;
    if (threadIdx.x == 0) out[0] = 0.0f;
    if (warp < SEGC) {
        float p = 0.0f;
        for (int e = lane; e < 100; e += 32) {
            float v = S[warp * 100 + e];
            p = fmaf(v, v, p);
        }
        p += __shfl_xor_sync(0xffffffffu, p, 16);
        p += __shfl_xor_sync(0xffffffffu, p, 8);
        p += __shfl_xor_sync(0xffffffffu, p, 4);
        p += __shfl_xor_sync(0xffffffffu, p, 2);
        p += __shfl_xor_sync(0xffffffffu, p, 1);
        if (lane == 0) g_yy[warp] = p;
    }
}

__global__ __launch_bounds__(TPB)
void softmin_kernel(const float* __restrict__ x, const float* __restrict__ S,
                    float* __restrict__ out, int Q, int W, float invW)
{
    extern __shared__ float smem[];
    float* sx = smem;              // TILE_F floats: staged window data
    float* ss = smem + TILE_F;     // 500 floats: -2*S
    __shared__ float sred[TPB / 32];

    const int t = threadIdx.x;

    // ---- stage x tile (coalesced float2) ----
    {
        const size_t gbase2 = (size_t)blockIdx.x * (WPB * 250 / 2); // f2 index
        const float2* g2 = reinterpret_cast<const float2*>(x);
        const size_t q2 = (size_t)(Q >> 1);
        #pragma unroll 4
        for (int idx = t; idx < TILE_F / 2; idx += TPB) {
            size_t g = gbase2 + idx;
            float2 v = (g < q2) ? g2[g] : make_float2(0.0f, 0.0f);
            reinterpret_cast<float2*>(sx)[idx] = v;
        }
        for (int idx = t; idx < 500; idx += TPB)
            ss[idx] = -2.0f * S[idx];
    }

    // yy (tiny, L2-hot)
    float yy0 = g_yy[0], yy1 = g_yy[1], yy2 = g_yy[2], yy3 = g_yy[3], yy4 = g_yy[4];

    __syncthreads();

    // ---- per-window accumulation ----
    const int h    = t & 1;
    const int wloc = t >> 1;
    const int w    = blockIdx.x * WPB + wloc;

    const float* xb = sx + wloc * 250 + h * 50;
    const float* sb = ss + h * 50;

    float axx0 = 0, axx1 = 0, axx2 = 0, axx3 = 0, axx4 = 0;
    float a0 = 0, a1 = 0, a2 = 0, a3 = 0, a4 = 0, a5 = 0, a6 = 0;
    float a7 = 0, a8 = 0, a9 = 0, a10 = 0, a11 = 0, a12 = 0;

    #pragma unroll 5
    for (int m = 0; m < 50; ++m) {
        int e = m + h;                 // h=1 rotates by 1 -> odd addr offset vs
        e = (e >= 50) ? e - 50 : e;    // h=0 lanes -> conflict-free banks

        float xv0 = xb[0 * 100 + e];
        float xv1 = xb[1 * 100 + e];
        float xv2 = xb[2 * 100 + e];
        float xv3 = xb[3 * 100 + e];
        float xv4 = xb[4 * 100 + e];
        float sv0 = sb[0 * 100 + e];   // holds -2*S
        float sv1 = sb[1 * 100 + e];
        float sv2 = sb[2 * 100 + e];
        float sv3 = sb[3 * 100 + e];
        float sv4 = sb[4 * 100 + e];

        axx0 = fmaf(xv0, xv0, axx0);
        axx1 = fmaf(xv1, xv1, axx1);
        axx2 = fmaf(xv2, xv2, axx2);
        axx3 = fmaf(xv3, xv3, axx3);
        axx4 = fmaf(xv4, xv4, axx4);

        a0  = fmaf(xv0, sv0, a0);    // (0,0)
        a1  = fmaf(xv0, sv1, a1);    // (0,1)
        a2  = fmaf(xv1, sv0, a2);    // (1,0)
        a3  = fmaf(xv1, sv1, a3);    // (1,1)
        a4  = fmaf(xv1, sv2, a4);    // (1,2)
        a5  = fmaf(xv2, sv1, a5);    // (2,1)
        a6  = fmaf(xv2, sv2, a6);    // (2,2)
        a7  = fmaf(xv2, sv3, a7);    // (2,3)
        a8  = fmaf(xv3, sv2, a8);    // (3,2)
        a9  = fmaf(xv3, sv3, a9);    // (3,3)
        a10 = fmaf(xv3, sv4, a10);   // (3,4)
        a11 = fmaf(xv4, sv3, a11);   // (4,3)
        a12 = fmaf(xv4, sv4, a12);   // (4,4)
    }

    // combine the two half-window threads (lane pair)
    const unsigned FM = 0xffffffffu;
    axx0 += __shfl_xor_sync(FM, axx0, 1);
    axx1 += __shfl_xor_sync(FM, axx1, 1);
    axx2 += __shfl_xor_sync(FM, axx2, 1);
    axx3 += __shfl_xor_sync(FM, axx3, 1);
    axx4 += __shfl_xor_sync(FM, axx4, 1);
    a0  += __shfl_xor_sync(FM, a0, 1);
    a1  += __shfl_xor_sync(FM, a1, 1);
    a2  += __shfl_xor_sync(FM, a2, 1);
    a3  += __shfl_xor_sync(FM, a3, 1);
    a4  += __shfl_xor_sync(FM, a4, 1);
    a5  += __shfl_xor_sync(FM, a5, 1);
    a6  += __shfl_xor_sync(FM, a6, 1);
    a7  += __shfl_xor_sync(FM, a7, 1);
    a8  += __shfl_xor_sync(FM, a8, 1);
    a9  += __shfl_xor_sync(FM, a9, 1);
    a10 += __shfl_xor_sync(FM, a10, 1);
    a11 += __shfl_xor_sync(FM, a11, 1);
    a12 += __shfl_xor_sync(FM, a12, 1);

    // C[i][jo], jo = j - i + 1 ; a* already carry the -2 factor
    float C[SEGC][3];
    C[0][0] = 0.0f;            C[0][1] = axx0 + yy0 + a0;  C[0][2] = axx0 + yy1 + a1;
    C[1][0] = axx1 + yy0 + a2; C[1][1] = axx1 + yy1 + a3;  C[1][2] = axx1 + yy2 + a4;
    C[2][0] = axx2 + yy1 + a5; C[2][1] = axx2 + yy2 + a6;  C[2][2] = axx2 + yy3 + a7;
    C[3][0] = axx3 + yy2 + a8; C[3][1] = axx3 + yy3 + a9;  C[3][2] = axx3 + yy4 + a10;
    C[4][0] = axx4 + yy3 + a11; C[4][1] = axx4 + yy4 + a12; C[4][2] = 0.0f;

    // banded DTW in registers
    const float INF = CUDART_INF_F;
    float row[SEGC + 1];
    row[0] = 0.0f;
    #pragma unroll
    for (int r = 1; r <= SEGC; ++r) row[r] = INF;
    #pragma unroll
    for (int i = 0; i < SEGC; ++i) {
        float nrow[SEGC + 1];
        #pragma unroll
        for (int r = 0; r <= SEGC; ++r) nrow[r] = INF;
        const int lo = (i > 0) ? (i - 1) : 0;
        const int hi = (i + 1 < SEGC) ? (i + 1) : (SEGC - 1);
        #pragma unroll
        for (int j = 0; j < SEGC; ++j) {
            if (j >= lo && j <= hi) {
                float prev = fminf(fminf(row[j + 1], nrow[j]), row[j]);
                nrow[j + 1] = C[i][j - i + 1] + prev;
            }
        }
        #pragma unroll
        for (int r = 0; r <= SEGC; ++r) row[r] = nrow[r];
    }

    float xi = __expf(-0.01f * sqrtf(row[SEGC]));
    float v = (h == 0 && w < W) ? xi : 0.0f;

    // block reduce -> one atomicAdd
    v += __shfl_xor_sync(FM, v, 16);
    v += __shfl_xor_sync(FM, v, 8);
    v += __shfl_xor_sync(FM, v, 4);
    v += __shfl_xor_sync(FM, v, 2);
    v += __shfl_xor_sync(FM, v, 1);
    const int lane = t & 31, warp = t >> 5;
    if (lane == 0) sred[warp] = v;
    __syncthreads();
    if (t == 0)
        atomicAdd(out, (sred[0] + sred[1] + sred[2] + sred[3]) * invW);
}

extern "C" void kernel_launch(void* const* d_in, const int* in_sizes, int n_in,
                              void* d_out, int out_size)
{
    const float* x = (const float*)d_in[0];
    const float* S = (const float*)d_in[1];
    float* out = (float*)d_out;

    const int Q    = in_sizes[0];
    const int L    = in_sizes[1];       // 500
    const int step = L / 2;             // 250
    const int W    = (Q - L + step - 1) / step;   // 79998
    const float invW = 1.0f / (float)W;

    const int smem_bytes = (TILE_F + 500) * sizeof(float);   // 67000
    cudaFuncSetAttribute(softmin_kernel,
                         cudaFuncAttributeMaxDynamicSharedMemorySize, smem_bytes);

    init_kernel<<<1, 160>>>(S, out);
    const int blocks = (W + WPB - 1) / WPB;   // 1250
    softmin_kernel<<<blocks, TPB, smem_bytes>>>(x, S, out, Q, W, invW);
}

// round 4
// speedup vs baseline: 1.3131x; 1.3131x over previous
#include <cuda_runtime.h>
#include <math_constants.h>

// SoftMinLayer: W = 79998 windows (len 500, step 250); 5 segments of 100;
// banded DTW (|i-j|<=1) over squared-L2 costs; out = mean(exp(-0.01*sqrt(d))).
//
// TWO windows per warp: lanes 0-15 handle window 2p, lanes 16-31 window 2p+1.
// Each 16-lane half accumulates the 13 band cells with packed f32x2 FMA over
// 4 element slices; a width-16 fold tree (14 shfl) reduces all 13 cells at
// once; width-16 broadcasts feed a fully-unrolled register DTW. All fixed
// per-window overhead (fold/broadcast/DTW/exp) is shared by 2 windows.

#define SEGC   5
#define TPB    256
#define NW     8          // warps per block
#define BLOCKS 444        // 3 * 148, persistent

typedef unsigned long long u64;

__device__ __forceinline__ u64 f2_fma(u64 a, u64 b, u64 c) {
    u64 d; asm("fma.rn.f32x2 %0, %1, %2, %3;" : "=l"(d) : "l"(a), "l"(b), "l"(c)); return d;
}
__device__ __forceinline__ u64 f2_add(u64 a, u64 b) {
    u64 d; asm("add.rn.f32x2 %0, %1, %2;" : "=l"(d) : "l"(a), "l"(b)); return d;
}
__device__ __forceinline__ float f2_hadd(u64 v) {
    float lo, hi; asm("mov.b64 {%0, %1}, %2;" : "=f"(lo), "=f"(hi) : "l"(v));
    return lo + hi;
}

// Pair two reduction streams A,B at butterfly offset o (o<16: stays in half).
__device__ __forceinline__ float foldstep(float A, float B, bool p, int o) {
    float v = p ? B : A;
    float u = p ? A : B;
    return v + __shfl_xor_sync(0xffffffffu, u, o);
}
// After the 4-level width-16 fold, cell n sits at lane (within each half):
#define SRCLANE16(n) ((((n) & 1) << 3) | ((((n) >> 1) & 1) << 2) | \
                      ((((n) >> 2) & 1) << 1) | (((n) >> 3) & 1))

__global__ void zero_kernel(float* out) { out[0] = 0.0f; }

__global__ __launch_bounds__(TPB, 3)
void softmin_kernel(const float* __restrict__ x, const float* __restrict__ S,
                    float* __restrict__ out, int W, float invW)
{
    __shared__ float ssf[SEGC * 128];   // -S, each segment padded 100 -> 128 (zeros)
    __shared__ float sred[NW];

    const int t = threadIdx.x;
    for (int i = t; i < SEGC * 128; i += TPB) {
        int seg = i >> 7, off = i & 127;
        ssf[i] = (off < 100) ? -S[seg * 100 + off] : 0.0f;
    }
    __syncthreads();
    const u64* ss2 = reinterpret_cast<const u64*>(ssf);   // [seg*64 + idx]

    const int lane = t & 31, warp = t >> 5;
    const int h    = lane >> 4;        // which window of the pair
    const int sub  = lane & 15;        // lane within half
    const int gw   = blockIdx.x * NW + warp;
    const int TW   = gridDim.x * NW;
    const int NP   = (W + 1) >> 1;

    const bool p8 = (lane & 8) != 0;
    const bool p4 = (lane & 4) != 0;
    const bool p2 = (lane & 2) != 0;
    const bool p1 = (lane & 1) != 0;

    float xsum = 0.0f;

    for (int p = gw; p < NP; p += TW) {
        const int w  = 2 * p + h;
        const int wc = (w < W) ? w : (W - 1);
        const u64* xw = reinterpret_cast<const u64*>(x) + (size_t)wc * 125u;

        u64 acc[13];
#pragma unroll
        for (int c = 0; c < 13; ++c) acc[c] = 0ull;

        // cell ids: (m,m)=3m ; (m,m-1)=3m-1 ; (m-1,m)=3m-2
        u64 xp[4], sp[4];
#pragma unroll
        for (int m = 0; m < SEGC; ++m) {
            u64 xv[4], sv[4];
#pragma unroll
            for (int k = 0; k < 4; ++k) {
                const int idx = sub + 16 * k;
                xv[k] = (idx < 50) ? xw[m * 50 + idx] : 0ull;   // 50 f2 per segment
                sv[k] = ss2[m * 64 + idx];                      // zero-padded
            }
            // (m, m): x_m vs s_m
#pragma unroll
            for (int k = 0; k < 4; ++k) {
                u64 d = f2_add(xv[k], sv[k]);
                acc[3 * m] = f2_fma(d, d, acc[3 * m]);
            }
            if (m > 0) {
                // (m, m-1): x_m vs s_{m-1}
#pragma unroll
                for (int k = 0; k < 4; ++k) {
                    u64 d = f2_add(xv[k], sp[k]);
                    acc[3 * m - 1] = f2_fma(d, d, acc[3 * m - 1]);
                }
                // (m-1, m): x_{m-1} vs s_m
#pragma unroll
                for (int k = 0; k < 4; ++k) {
                    u64 d = f2_add(xp[k], sv[k]);
                    acc[3 * m - 2] = f2_fma(d, d, acc[3 * m - 2]);
                }
            }
#pragma unroll
            for (int k = 0; k < 4; ++k) { xp[k] = xv[k]; sp[k] = sv[k]; }
        }

        // horizontal f32x2 add -> 13 per-lane partials
        float a0  = f2_hadd(acc[0]),  a1  = f2_hadd(acc[1]),  a2  = f2_hadd(acc[2]);
        float a3  = f2_hadd(acc[3]),  a4  = f2_hadd(acc[4]),  a5  = f2_hadd(acc[5]);
        float a6  = f2_hadd(acc[6]),  a7  = f2_hadd(acc[7]),  a8  = f2_hadd(acc[8]);
        float a9  = f2_hadd(acc[9]),  a10 = f2_hadd(acc[10]), a11 = f2_hadd(acc[11]);
        float a12 = f2_hadd(acc[12]);

        // width-16 fold tree: 14 shfl reduce all 13 cells (per half)
        float q0 = foldstep(a0,  a1,  p8, 8);
        float q1 = foldstep(a2,  a3,  p8, 8);
        float q2 = foldstep(a4,  a5,  p8, 8);
        float q3 = foldstep(a6,  a7,  p8, 8);
        float q4 = foldstep(a8,  a9,  p8, 8);
        float q5 = foldstep(a10, a11, p8, 8);
        float q6 = foldstep(a12, 0.0f, p8, 8);

        float r0 = foldstep(q0, q1, p4, 4);
        float r1 = foldstep(q2, q3, p4, 4);
        float r2 = foldstep(q4, q5, p4, 4);
        float r3 = foldstep(q6, 0.0f, p4, 4);

        float t0 = foldstep(r0, r1, p2, 2);
        float t1 = foldstep(r2, r3, p2, 2);

        float fin = foldstep(t0, t1, p1, 1);

        // broadcast within each 16-lane half
        float C13[13];
#pragma unroll
        for (int n = 0; n < 13; ++n)
            C13[n] = __shfl_sync(0xffffffffu, fin, SRCLANE16(n), 16);

        float C[SEGC][3];
#pragma unroll
        for (int i = 0; i < SEGC; ++i) {
#pragma unroll
            for (int jo = 0; jo < 3; ++jo) {
                const int j = i + jo - 1;
                if (j >= 0 && j < SEGC) {
                    const int c = (j == i) ? 3 * i : ((j < i) ? 3 * i - 1 : 3 * i + 1);
                    C[i][jo] = C13[c];
                } else {
                    C[i][jo] = 0.0f;
                }
            }
        }

        // banded DTW, fully unrolled in registers
        const float INF = CUDART_INF_F;
        float row[SEGC + 1];
        row[0] = 0.0f;
#pragma unroll
        for (int r = 1; r <= SEGC; ++r) row[r] = INF;
#pragma unroll
        for (int i = 0; i < SEGC; ++i) {
            float nrow[SEGC + 1];
#pragma unroll
            for (int r = 0; r <= SEGC; ++r) nrow[r] = INF;
            const int lo = (i > 0) ? (i - 1) : 0;
            const int hi = (i + 1 < SEGC) ? (i + 1) : (SEGC - 1);
#pragma unroll
            for (int j = 0; j < SEGC; ++j) {
                if (j >= lo && j <= hi) {
                    float prev = fminf(fminf(row[j + 1], nrow[j]), row[j]);
                    nrow[j + 1] = C[i][j - i + 1] + prev;
                }
            }
#pragma unroll
            for (int r = 0; r <= SEGC; ++r) row[r] = nrow[r];
        }

        float xi = __expf(-0.01f * sqrtf(row[SEGC]));
        if (w < W) xsum += xi;        // uniform within each half
    }

    // epilogue: lane 0 of each half carries its half's sum
    float v = (sub == 0) ? xsum : 0.0f;
    v += __shfl_xor_sync(0xffffffffu, v, 16);
    v += __shfl_xor_sync(0xffffffffu, v, 8);
    v += __shfl_xor_sync(0xffffffffu, v, 4);
    v += __shfl_xor_sync(0xffffffffu, v, 2);
    v += __shfl_xor_sync(0xffffffffu, v, 1);
    if ((t & 31) == 0) sred[warp] = v;
    __syncthreads();
    if (t == 0) {
        float s = 0.0f;
#pragma unroll
        for (int i = 0; i < NW; ++i) s += sred[i];
        atomicAdd(out, s * invW);
    }
}

extern "C" void kernel_launch(void* const* d_in, const int* in_sizes, int n_in,
                              void* d_out, int out_size)
{
    const float* x = (const float*)d_in[0];
    const float* S = (const float*)d_in[1];
    float* out = (float*)d_out;

    const int Q    = in_sizes[0];
    const int L    = in_sizes[1];       // 500
    const int step = L / 2;             // 250
    const int W    = (Q - L + step - 1) / step;   // 79998
    const float invW = 1.0f / (float)W;

    zero_kernel<<<1, 1>>>(out);
    softmin_kernel<<<BLOCKS, TPB>>>(x, S, out, W, invW);
}